// round 12
// baseline (speedup 1.0000x reference)
#include <cuda_runtime.h>
#include <cuda_bf16.h>
#include <math.h>

// Problem constants
#define S_LEN 2048
#define HID   2048
#define NH    32
#define KVH   8
#define HD    64          // head dim
#define GQ    4           // G = NH/KVH
#define QKV_N 3072        // (NH + 2*KVH) * HD

// Scratch (static device allocation — allowed)
__device__ float g_qkv[S_LEN * QKV_N];     // [2048, 3072]
__device__ float g_attn[S_LEN * HID];      // [2048, 2048]

// ---------------------------------------------------------------------------
// SGEMM NT:  C[M,N] = A[M,K] * B[N,K]^T   (both row-major, K contiguous)
// 128x128 tile, BK=16, 256 threads, 8x8 per thread (2x2 blocks of 4x4).
// All dims assumed divisible by tile sizes (true for this problem).
// ---------------------------------------------------------------------------
#define BM 128
#define BN 128
#define BK 16

__global__ __launch_bounds__(256) void sgemm_nt(
    const float* __restrict__ A, const float* __restrict__ B,
    float* __restrict__ C, int M, int N, int K)
{
    __shared__ float As[BK][BM];
    __shared__ float Bs[BK][BN];

    const int m0 = blockIdx.y * BM;
    const int n0 = blockIdx.x * BN;
    const int tid = threadIdx.x;
    const int tx = tid & 15;        // 0..15
    const int ty = tid >> 4;        // 0..15

    float acc[8][8];
#pragma unroll
    for (int i = 0; i < 8; i++)
#pragma unroll
        for (int j = 0; j < 8; j++) acc[i][j] = 0.f;

    for (int k0 = 0; k0 < K; k0 += BK) {
        // Load tiles: 128 rows x 16 k each, float4 per thread x2
#pragma unroll
        for (int l = 0; l < 2; l++) {
            int idx = tid + l * 256;     // 0..511
            int row = idx >> 2;          // 0..127
            int kg  = (idx & 3) << 2;    // 0,4,8,12
            float4 va = *(const float4*)&A[(size_t)(m0 + row) * K + k0 + kg];
            As[kg + 0][row] = va.x; As[kg + 1][row] = va.y;
            As[kg + 2][row] = va.z; As[kg + 3][row] = va.w;
            float4 vb = *(const float4*)&B[(size_t)(n0 + row) * K + k0 + kg];
            Bs[kg + 0][row] = vb.x; Bs[kg + 1][row] = vb.y;
            Bs[kg + 2][row] = vb.z; Bs[kg + 3][row] = vb.w;
        }
        __syncthreads();

#pragma unroll
        for (int kk = 0; kk < BK; kk++) {
            float4 a0 = *(const float4*)&As[kk][ty * 4];
            float4 a1 = *(const float4*)&As[kk][64 + ty * 4];
            float4 b0 = *(const float4*)&Bs[kk][tx * 4];
            float4 b1 = *(const float4*)&Bs[kk][64 + tx * 4];
            float a[8] = {a0.x, a0.y, a0.z, a0.w, a1.x, a1.y, a1.z, a1.w};
            float b[8] = {b0.x, b0.y, b0.z, b0.w, b1.x, b1.y, b1.z, b1.w};
#pragma unroll
            for (int i = 0; i < 8; i++)
#pragma unroll
                for (int j = 0; j < 8; j++)
                    acc[i][j] = fmaf(a[i], b[j], acc[i][j]);
        }
        __syncthreads();
    }

    // Write back
#pragma unroll
    for (int ih = 0; ih < 2; ih++) {
#pragma unroll
        for (int ii = 0; ii < 4; ii++) {
            int r = m0 + ih * 64 + ty * 4 + ii;
            int ai = ih * 4 + ii;
#pragma unroll
            for (int jh = 0; jh < 2; jh++) {
                float4 v = make_float4(acc[ai][jh * 4 + 0], acc[ai][jh * 4 + 1],
                                       acc[ai][jh * 4 + 2], acc[ai][jh * 4 + 3]);
                *(float4*)&C[(size_t)r * N + n0 + jh * 64 + tx * 4] = v;
            }
        }
    }
}

// ---------------------------------------------------------------------------
// RoPE: applied in-place to Q (32 heads) and K (8 heads) inside g_qkv.
// One thread per (token, head-slot, pair-index).
// ---------------------------------------------------------------------------
__global__ void rope_kernel(float* __restrict__ qkv)
{
    int idx = blockIdx.x * blockDim.x + threadIdx.x;
    const int total = S_LEN * (NH + KVH) * (HD / 2);
    if (idx >= total) return;

    int i  = idx & 31;                    // pair index 0..31
    int hh = (idx >> 5) % (NH + KVH);     // 0..39 (0..31 = Q heads, 32..39 = K heads)
    int s  = idx / ((NH + KVH) * 32);

    // inv_freq = 10000^(-i/32); compute in double, round to fp32 (matches jnp fp32)
    double ifd = exp(-9.210340371976184 * (double)i / 32.0);  // ln(10000)
    float inv_freq = (float)ifd;
    float fr = (float)s * inv_freq;
    float c = cosf(fr);
    float sn = sinf(fr);

    size_t base = (size_t)s * QKV_N +
                  (hh < NH ? hh * HD : NH * HD + (hh - NH) * HD);
    float x1 = qkv[base + i];
    float x2 = qkv[base + 32 + i];
    qkv[base + i]      = x1 * c - x2 * sn;
    qkv[base + 32 + i] = x2 * c + x1 * sn;
}

// ---------------------------------------------------------------------------
// Causal GQA attention, flash style.
// Block: 128 threads, each thread = one query row. grid = (S/128, NH).
// K/V tiles of 64 rows staged in smem; q + output accumulator in registers.
// ---------------------------------------------------------------------------
#define AT_BQ 128
#define AT_BK 64

__global__ __launch_bounds__(128) void attn_kernel(
    const float* __restrict__ qkv, float* __restrict__ attn_out)
{
    const int h   = blockIdx.y;        // head 0..31
    const int kvh = h >> 2;            // GQA group
    const int qb  = blockIdx.x;
    const int tid = threadIdx.x;
    const int q_row = qb * AT_BQ + tid;

    __shared__ float Ks[AT_BK][HD];
    __shared__ float Vs[AT_BK][HD];

    // Load q into registers
    float q[HD];
    {
        const float* qp = qkv + (size_t)q_row * QKV_N + h * HD;
#pragma unroll
        for (int d4 = 0; d4 < HD / 4; d4++) {
            float4 v = *(const float4*)&qp[d4 * 4];
            q[d4 * 4 + 0] = v.x; q[d4 * 4 + 1] = v.y;
            q[d4 * 4 + 2] = v.z; q[d4 * 4 + 3] = v.w;
        }
    }

    float o[HD];
#pragma unroll
    for (int d = 0; d < HD; d++) o[d] = 0.f;
    float m = -1e30f, l = 0.f;
    const float scale = 0.125f;   // 1/sqrt(64)

    const int ntiles = 2 * qb + 2;
    for (int kt = 0; kt < ntiles; kt++) {
        __syncthreads();
        // Stage K/V tile: 64 rows x 64 cols each; 8 float4 per thread per tensor
#pragma unroll
        for (int i = 0; i < 8; i++) {
            int idx = tid + i * 128;      // 0..1023
            int row = idx >> 4;           // 0..63
            int c4  = (idx & 15) << 2;    // 0..60
            const float* kp = qkv + (size_t)(kt * AT_BK + row) * QKV_N
                              + NH * HD + kvh * HD + c4;
            *(float4*)&Ks[row][c4] = *(const float4*)kp;
            *(float4*)&Vs[row][c4] = *(const float4*)(kp + KVH * HD);
        }
        __syncthreads();

        int jmax = q_row - kt * AT_BK + 1;
        if (jmax > AT_BK) jmax = AT_BK;

        for (int j = 0; j < jmax; j++) {
            const float4* kr = (const float4*)Ks[j];
            float s = 0.f;
#pragma unroll
            for (int d4 = 0; d4 < HD / 4; d4++) {
                float4 kv4 = kr[d4];
                s = fmaf(q[d4 * 4 + 0], kv4.x, s);
                s = fmaf(q[d4 * 4 + 1], kv4.y, s);
                s = fmaf(q[d4 * 4 + 2], kv4.z, s);
                s = fmaf(q[d4 * 4 + 3], kv4.w, s);
            }
            s *= scale;
            if (s > m) {
                float alpha = expf(m - s);
                m = s;
                l *= alpha;
#pragma unroll
                for (int d = 0; d < HD; d++) o[d] *= alpha;
            }
            float p = expf(s - m);
            l += p;
            const float4* vr = (const float4*)Vs[j];
#pragma unroll
            for (int d4 = 0; d4 < HD / 4; d4++) {
                float4 vv = vr[d4];
                o[d4 * 4 + 0] = fmaf(p, vv.x, o[d4 * 4 + 0]);
                o[d4 * 4 + 1] = fmaf(p, vv.y, o[d4 * 4 + 1]);
                o[d4 * 4 + 2] = fmaf(p, vv.z, o[d4 * 4 + 2]);
                o[d4 * 4 + 3] = fmaf(p, vv.w, o[d4 * 4 + 3]);
            }
        }
    }

    float inv_l = 1.f / l;
    float* op = attn_out + (size_t)q_row * HID + h * HD;
#pragma unroll
    for (int d4 = 0; d4 < HD / 4; d4++) {
        float4 v = make_float4(o[d4 * 4 + 0] * inv_l, o[d4 * 4 + 1] * inv_l,
                               o[d4 * 4 + 2] * inv_l, o[d4 * 4 + 3] * inv_l);
        *(float4*)&op[d4 * 4] = v;
    }
}

// ---------------------------------------------------------------------------
// Launch
// ---------------------------------------------------------------------------
extern "C" void kernel_launch(void* const* d_in, const int* in_sizes, int n_in,
                              void* d_out, int out_size)
{
    const float* x     = (const float*)d_in[0];   // [1,2048,2048]
    const float* w_qkv = (const float*)d_in[1];   // [3072,2048]
    const float* w_o   = (const float*)d_in[2];   // [2048,2048]
    float* out = (float*)d_out;                   // [1,2048,2048]

    float* qkv_buf = nullptr;
    float* attn_buf = nullptr;
    cudaGetSymbolAddress((void**)&qkv_buf, g_qkv);
    cudaGetSymbolAddress((void**)&attn_buf, g_attn);

    // 1) QKV projection: [2048,2048] x [3072,2048]^T -> [2048,3072]
    {
        dim3 grid(QKV_N / BN, S_LEN / BM);
        sgemm_nt<<<grid, 256>>>(x, w_qkv, qkv_buf, S_LEN, QKV_N, HID);
    }

    // 2) RoPE on Q and K in place
    {
        int total = S_LEN * (NH + KVH) * (HD / 2);
        rope_kernel<<<(total + 255) / 256, 256>>>(qkv_buf);
    }

    // 3) Causal GQA attention -> [2048, 2048]
    {
        dim3 grid(S_LEN / AT_BQ, NH);
        attn_kernel<<<grid, 128>>>(qkv_buf, attn_buf);
    }

    // 4) Output projection: [2048,2048] x [2048,2048]^T -> d_out
    {
        dim3 grid(HID / BN, S_LEN / BM);
        sgemm_nt<<<grid, 256>>>(attn_buf, w_o, out, S_LEN, HID, HID);
    }
}

// round 13
// speedup vs baseline: 1.0498x; 1.0498x over previous
#include <cuda_runtime.h>
#include <cuda_bf16.h>
#include <math.h>

// Problem constants
#define S_LEN 2048
#define HID   2048
#define NH    32
#define KVH   8
#define HD    64          // head dim
#define GQ    4           // G = NH/KVH
#define QKV_N 3072        // (NH + 2*KVH) * HD

// Scratch (static device allocation — allowed)
__device__ float g_qkv[S_LEN * QKV_N];     // [2048, 3072]
__device__ float g_attn[S_LEN * HID];      // [2048, 2048]

// ---------------------------------------------------------------------------
// SGEMM NT:  C[M,N] = A[M,K] * B[N,K]^T   (both row-major, K contiguous)
// 128x128 tile, BK=16, 256 threads, 8x8 per thread.
// ---------------------------------------------------------------------------
#define BM 128
#define BN 128
#define BK 16

__global__ __launch_bounds__(256) void sgemm_nt(
    const float* __restrict__ A, const float* __restrict__ B,
    float* __restrict__ C, int M, int N, int K)
{
    __shared__ float As[BK][BM];
    __shared__ float Bs[BK][BN];

    const int m0 = blockIdx.y * BM;
    const int n0 = blockIdx.x * BN;
    const int tid = threadIdx.x;
    const int tx = tid & 15;
    const int ty = tid >> 4;

    float acc[8][8];
#pragma unroll
    for (int i = 0; i < 8; i++)
#pragma unroll
        for (int j = 0; j < 8; j++) acc[i][j] = 0.f;

    for (int k0 = 0; k0 < K; k0 += BK) {
#pragma unroll
        for (int l = 0; l < 2; l++) {
            int idx = tid + l * 256;
            int row = idx >> 2;
            int kg  = (idx & 3) << 2;
            float4 va = *(const float4*)&A[(size_t)(m0 + row) * K + k0 + kg];
            As[kg + 0][row] = va.x; As[kg + 1][row] = va.y;
            As[kg + 2][row] = va.z; As[kg + 3][row] = va.w;
            float4 vb = *(const float4*)&B[(size_t)(n0 + row) * K + k0 + kg];
            Bs[kg + 0][row] = vb.x; Bs[kg + 1][row] = vb.y;
            Bs[kg + 2][row] = vb.z; Bs[kg + 3][row] = vb.w;
        }
        __syncthreads();

#pragma unroll
        for (int kk = 0; kk < BK; kk++) {
            float4 a0 = *(const float4*)&As[kk][ty * 4];
            float4 a1 = *(const float4*)&As[kk][64 + ty * 4];
            float4 b0 = *(const float4*)&Bs[kk][tx * 4];
            float4 b1 = *(const float4*)&Bs[kk][64 + tx * 4];
            float a[8] = {a0.x, a0.y, a0.z, a0.w, a1.x, a1.y, a1.z, a1.w};
            float b[8] = {b0.x, b0.y, b0.z, b0.w, b1.x, b1.y, b1.z, b1.w};
#pragma unroll
            for (int i = 0; i < 8; i++)
#pragma unroll
                for (int j = 0; j < 8; j++)
                    acc[i][j] = fmaf(a[i], b[j], acc[i][j]);
        }
        __syncthreads();
    }

#pragma unroll
    for (int ih = 0; ih < 2; ih++) {
#pragma unroll
        for (int ii = 0; ii < 4; ii++) {
            int r = m0 + ih * 64 + ty * 4 + ii;
            int ai = ih * 4 + ii;
#pragma unroll
            for (int jh = 0; jh < 2; jh++) {
                float4 v = make_float4(acc[ai][jh * 4 + 0], acc[ai][jh * 4 + 1],
                                       acc[ai][jh * 4 + 2], acc[ai][jh * 4 + 3]);
                *(float4*)&C[(size_t)r * N + n0 + jh * 64 + tx * 4] = v;
            }
        }
    }
}

// ---------------------------------------------------------------------------
// RoPE (in place on Q heads 0..31 and K heads 32..39 of g_qkv)
// ---------------------------------------------------------------------------
__global__ void rope_kernel(float* __restrict__ qkv)
{
    int idx = blockIdx.x * blockDim.x + threadIdx.x;
    const int total = S_LEN * (NH + KVH) * (HD / 2);
    if (idx >= total) return;

    int i  = idx & 31;
    int hh = (idx >> 5) % (NH + KVH);
    int s  = idx / ((NH + KVH) * 32);

    double ifd = exp(-9.210340371976184 * (double)i / 32.0);
    float inv_freq = (float)ifd;
    float fr = (float)s * inv_freq;
    float c = cosf(fr);
    float sn = sinf(fr);

    size_t base = (size_t)s * QKV_N +
                  (hh < NH ? hh * HD : NH * HD + (hh - NH) * HD);
    float x1 = qkv[base + i];
    float x2 = qkv[base + 32 + i];
    qkv[base + i]      = x1 * c - x2 * sn;
    qkv[base + 32 + i] = x2 * c + x1 * sn;
}

// ---------------------------------------------------------------------------
// Causal GQA attention, flash style, chunked-ILP version.
// Block: 128 threads, each thread = one query row. grid = (S/128, NH).
// Inner loop processes keys in chunks of 8 with 8 independent accumulators.
// ---------------------------------------------------------------------------
#define AT_BQ 128
#define AT_BK 64
#define CH 8

__global__ __launch_bounds__(128) void attn_kernel(
    const float* __restrict__ qkv, float* __restrict__ attn_out)
{
    const int h   = blockIdx.y;
    const int kvh = h >> 2;
    const int qb  = gridDim.x - 1 - blockIdx.x;   // heavy blocks launch first
    const int tid = threadIdx.x;
    const int q_row = qb * AT_BQ + tid;

    __shared__ float Ks[AT_BK][HD];
    __shared__ float Vs[AT_BK][HD];

    // Load q into registers, pre-scaled by 1/sqrt(D)
    float4 q4[HD / 4];
    {
        const float4* qp = (const float4*)(qkv + (size_t)q_row * QKV_N + h * HD);
#pragma unroll
        for (int d4 = 0; d4 < HD / 4; d4++) {
            float4 v = qp[d4];
            v.x *= 0.125f; v.y *= 0.125f; v.z *= 0.125f; v.w *= 0.125f;
            q4[d4] = v;
        }
    }

    float4 o4[HD / 4];
#pragma unroll
    for (int d4 = 0; d4 < HD / 4; d4++) o4[d4] = make_float4(0.f, 0.f, 0.f, 0.f);
    float m = -1e30f, l = 0.f;

    const int ntiles = 2 * qb + 2;
    for (int kt = 0; kt < ntiles; kt++) {
        __syncthreads();
        // Stage K/V tile: 64 rows x 64 cols each
#pragma unroll
        for (int i = 0; i < 8; i++) {
            int idx = tid + i * 128;
            int row = idx >> 4;
            int c4  = (idx & 15) << 2;
            const float* kp = qkv + (size_t)(kt * AT_BK + row) * QKV_N
                              + NH * HD + kvh * HD + c4;
            *(float4*)&Ks[row][c4] = *(const float4*)kp;
            *(float4*)&Vs[row][c4] = *(const float4*)(kp + KVH * HD);
        }
        __syncthreads();

        int rel = q_row - kt * AT_BK;       // last valid key index in tile
        if (rel < 0) continue;
        int jmax = rel + 1;
        if (jmax > AT_BK) jmax = AT_BK;

        for (int j0 = 0; j0 < jmax; j0 += CH) {
            // ---- scores: 8 independent accumulator chains ----
            float sc[CH];
#pragma unroll
            for (int jj = 0; jj < CH; jj++) sc[jj] = 0.f;

#pragma unroll
            for (int d4 = 0; d4 < HD / 4; d4++) {
                float4 qv = q4[d4];
#pragma unroll
                for (int jj = 0; jj < CH; jj++) {
                    float4 kv = *(const float4*)&Ks[j0 + jj][d4 * 4];
                    sc[jj] = fmaf(qv.x, kv.x, sc[jj]);
                    sc[jj] = fmaf(qv.y, kv.y, sc[jj]);
                    sc[jj] = fmaf(qv.z, kv.z, sc[jj]);
                    sc[jj] = fmaf(qv.w, kv.w, sc[jj]);
                }
            }

            // ---- causal mask + chunk max ----
            float mnew = m;
#pragma unroll
            for (int jj = 0; jj < CH; jj++) {
                sc[jj] = (j0 + jj <= rel) ? sc[jj] : -1e30f;
                mnew = fmaxf(mnew, sc[jj]);
            }

            // ---- rescale (once per chunk, only on new max) ----
            if (mnew > m) {
                float alpha = __expf(m - mnew);
                l *= alpha;
#pragma unroll
                for (int d4 = 0; d4 < HD / 4; d4++) {
                    o4[d4].x *= alpha; o4[d4].y *= alpha;
                    o4[d4].z *= alpha; o4[d4].w *= alpha;
                }
                m = mnew;
            }

            // ---- probabilities ----
            float p[CH];
            float ls = 0.f;
#pragma unroll
            for (int jj = 0; jj < CH; jj++) {
                p[jj] = __expf(sc[jj] - m);
                ls += p[jj];
            }
            l += ls;

            // ---- PV accumulate: independent per-component chains ----
#pragma unroll
            for (int d4 = 0; d4 < HD / 4; d4++) {
                float4 acc = o4[d4];
#pragma unroll
                for (int jj = 0; jj < CH; jj++) {
                    float4 vv = *(const float4*)&Vs[j0 + jj][d4 * 4];
                    acc.x = fmaf(p[jj], vv.x, acc.x);
                    acc.y = fmaf(p[jj], vv.y, acc.y);
                    acc.z = fmaf(p[jj], vv.z, acc.z);
                    acc.w = fmaf(p[jj], vv.w, acc.w);
                }
                o4[d4] = acc;
            }
        }
    }

    float inv_l = 1.f / l;
    float4* op = (float4*)(attn_out + (size_t)q_row * HID + h * HD);
#pragma unroll
    for (int d4 = 0; d4 < HD / 4; d4++) {
        float4 v = o4[d4];
        v.x *= inv_l; v.y *= inv_l; v.z *= inv_l; v.w *= inv_l;
        op[d4] = v;
    }
}

// ---------------------------------------------------------------------------
// Launch
// ---------------------------------------------------------------------------
extern "C" void kernel_launch(void* const* d_in, const int* in_sizes, int n_in,
                              void* d_out, int out_size)
{
    const float* x     = (const float*)d_in[0];   // [1,2048,2048]
    const float* w_qkv = (const float*)d_in[1];   // [3072,2048]
    const float* w_o   = (const float*)d_in[2];   // [2048,2048]
    float* out = (float*)d_out;                   // [1,2048,2048]

    float* qkv_buf = nullptr;
    float* attn_buf = nullptr;
    cudaGetSymbolAddress((void**)&qkv_buf, g_qkv);
    cudaGetSymbolAddress((void**)&attn_buf, g_attn);

    // 1) QKV projection: [2048,2048] x [3072,2048]^T -> [2048,3072]
    {
        dim3 grid(QKV_N / BN, S_LEN / BM);
        sgemm_nt<<<grid, 256>>>(x, w_qkv, qkv_buf, S_LEN, QKV_N, HID);
    }

    // 2) RoPE on Q and K in place
    {
        int total = S_LEN * (NH + KVH) * (HD / 2);
        rope_kernel<<<(total + 255) / 256, 256>>>(qkv_buf);
    }

    // 3) Causal GQA attention -> [2048, 2048]
    {
        dim3 grid(S_LEN / AT_BQ, NH);
        attn_kernel<<<grid, 128>>>(qkv_buf, attn_buf);
    }

    // 4) Output projection: [2048,2048] x [2048,2048]^T -> d_out
    {
        dim3 grid(HID / BN, S_LEN / BM);
        sgemm_nt<<<grid, 256>>>(attn_buf, w_o, out, S_LEN, HID, HID);
    }
}

// round 14
// speedup vs baseline: 1.1213x; 1.0681x over previous
#include <cuda_runtime.h>
#include <cuda_bf16.h>
#include <math.h>

// Problem constants
#define S_LEN 2048
#define HID   2048
#define NH    32
#define KVH   8
#define HD    64          // head dim
#define GQ    4           // G = NH/KVH
#define QKV_N 3072        // (NH + 2*KVH) * HD

// Scratch (static device allocation — allowed)
__device__ float g_qkv[S_LEN * QKV_N];     // [2048, 3072]
__device__ float g_attn[S_LEN * HID];      // [2048, 2048]

// ---------------------------------------------------------------------------
// SGEMM NT:  C[M,N] = A[M,K] * B[N,K]^T
// ---------------------------------------------------------------------------
#define BM 128
#define BN 128
#define BK 16

__global__ __launch_bounds__(256) void sgemm_nt(
    const float* __restrict__ A, const float* __restrict__ B,
    float* __restrict__ C, int M, int N, int K)
{
    __shared__ float As[BK][BM];
    __shared__ float Bs[BK][BN];

    const int m0 = blockIdx.y * BM;
    const int n0 = blockIdx.x * BN;
    const int tid = threadIdx.x;
    const int tx = tid & 15;
    const int ty = tid >> 4;

    float acc[8][8];
#pragma unroll
    for (int i = 0; i < 8; i++)
#pragma unroll
        for (int j = 0; j < 8; j++) acc[i][j] = 0.f;

    for (int k0 = 0; k0 < K; k0 += BK) {
#pragma unroll
        for (int l = 0; l < 2; l++) {
            int idx = tid + l * 256;
            int row = idx >> 2;
            int kg  = (idx & 3) << 2;
            float4 va = *(const float4*)&A[(size_t)(m0 + row) * K + k0 + kg];
            As[kg + 0][row] = va.x; As[kg + 1][row] = va.y;
            As[kg + 2][row] = va.z; As[kg + 3][row] = va.w;
            float4 vb = *(const float4*)&B[(size_t)(n0 + row) * K + k0 + kg];
            Bs[kg + 0][row] = vb.x; Bs[kg + 1][row] = vb.y;
            Bs[kg + 2][row] = vb.z; Bs[kg + 3][row] = vb.w;
        }
        __syncthreads();

#pragma unroll
        for (int kk = 0; kk < BK; kk++) {
            float4 a0 = *(const float4*)&As[kk][ty * 4];
            float4 a1 = *(const float4*)&As[kk][64 + ty * 4];
            float4 b0 = *(const float4*)&Bs[kk][tx * 4];
            float4 b1 = *(const float4*)&Bs[kk][64 + tx * 4];
            float a[8] = {a0.x, a0.y, a0.z, a0.w, a1.x, a1.y, a1.z, a1.w};
            float b[8] = {b0.x, b0.y, b0.z, b0.w, b1.x, b1.y, b1.z, b1.w};
#pragma unroll
            for (int i = 0; i < 8; i++)
#pragma unroll
                for (int j = 0; j < 8; j++)
                    acc[i][j] = fmaf(a[i], b[j], acc[i][j]);
        }
        __syncthreads();
    }

#pragma unroll
    for (int ih = 0; ih < 2; ih++) {
#pragma unroll
        for (int ii = 0; ii < 4; ii++) {
            int r = m0 + ih * 64 + ty * 4 + ii;
            int ai = ih * 4 + ii;
#pragma unroll
            for (int jh = 0; jh < 2; jh++) {
                float4 v = make_float4(acc[ai][jh * 4 + 0], acc[ai][jh * 4 + 1],
                                       acc[ai][jh * 4 + 2], acc[ai][jh * 4 + 3]);
                *(float4*)&C[(size_t)r * N + n0 + jh * 64 + tx * 4] = v;
            }
        }
    }
}

// ---------------------------------------------------------------------------
// RoPE (in place on Q heads 0..31 and K heads 32..39 of g_qkv)
// ---------------------------------------------------------------------------
__global__ void rope_kernel(float* __restrict__ qkv)
{
    int idx = blockIdx.x * blockDim.x + threadIdx.x;
    const int total = S_LEN * (NH + KVH) * (HD / 2);
    if (idx >= total) return;

    int i  = idx & 31;
    int hh = (idx >> 5) % (NH + KVH);
    int s  = idx / ((NH + KVH) * 32);

    double ifd = exp(-9.210340371976184 * (double)i / 32.0);
    float inv_freq = (float)ifd;
    float fr = (float)s * inv_freq;
    float c = cosf(fr);
    float sn = sinf(fr);

    size_t base = (size_t)s * QKV_N +
                  (hh < NH ? hh * HD : NH * HD + (hh - NH) * HD);
    float x1 = qkv[base + i];
    float x2 = qkv[base + 32 + i];
    qkv[base + i]      = x1 * c - x2 * sn;
    qkv[base + 32 + i] = x2 * c + x1 * sn;
}

// ---------------------------------------------------------------------------
// Flash attention, GEMM-tiled.
// CTA: 64 query rows x 1 head, 256 threads. K/V tiles of 32 keys.
// S-GEMM: thread tile 4q x 2k (tx=k, ty=q). PV-GEMM: thread tile 4q x 4d.
// Q,K staged d-major (transposed) in smem; V natural; P in smem [k][q].
// ---------------------------------------------------------------------------
#define QT 64
#define KT 32
#define PS_STRIDE 68   // QT + 4 pad, keeps 16B alignment, avoids bank conflicts

__global__ __launch_bounds__(256) void attn_kernel(
    const float* __restrict__ qkv, float* __restrict__ attn_out)
{
    const int h   = blockIdx.y;
    const int kvh = h >> 2;
    const int qt  = gridDim.x - 1 - blockIdx.x;   // heavy blocks first
    const int tid = threadIdx.x;
    const int tx  = tid & 15;     // k-dim: 2 cols each (S), d-dim: 4 each (PV)
    const int ty  = tid >> 4;     // q-dim: 4 rows each

    __shared__ float Qs[HD][QT];          // [d][q], scaled by 1/8
    __shared__ float Ks[HD][KT];          // [d][k]
    __shared__ float Vs[KT][HD];          // [k][d]
    __shared__ float Ps[KT][PS_STRIDE];   // [k][q]

    // ---- Stage Q transposed + pre-scaled (once) ----
#pragma unroll
    for (int l = 0; l < 4; l++) {
        int f  = tid + l * 256;           // 0..1023
        int q  = f & 63;
        int d4 = (f >> 6) * 4;            // 0..60
        float4 v = *(const float4*)&qkv[(size_t)(qt * QT + q) * QKV_N + h * HD + d4];
        Qs[d4 + 0][q] = v.x * 0.125f;
        Qs[d4 + 1][q] = v.y * 0.125f;
        Qs[d4 + 2][q] = v.z * 0.125f;
        Qs[d4 + 3][q] = v.w * 0.125f;
    }

    float4 o4[4];
#pragma unroll
    for (int i = 0; i < 4; i++) o4[i] = make_float4(0.f, 0.f, 0.f, 0.f);
    float m[4], l[4];
#pragma unroll
    for (int i = 0; i < 4; i++) { m[i] = -1e30f; l[i] = 0.f; }

    const int ntiles = 2 * qt + 2;
    for (int kt = 0; kt < ntiles; kt++) {
        __syncthreads();   // protect Ks/Vs from overwrite while PV still reading

        // ---- Stage K transposed: 32 tokens x 64 dims -> Ks[d][k] ----
#pragma unroll
        for (int ll = 0; ll < 2; ll++) {
            int f  = tid + ll * 256;      // 0..511
            int t  = f & 31;
            int d4 = (f >> 5) * 4;        // 0..60
            float4 v = *(const float4*)&qkv[(size_t)(kt * KT + t) * QKV_N
                                            + NH * HD + kvh * HD + d4];
            Ks[d4 + 0][t] = v.x;
            Ks[d4 + 1][t] = v.y;
            Ks[d4 + 2][t] = v.z;
            Ks[d4 + 3][t] = v.w;
        }
        // ---- Stage V natural: Vs[k][d] ----
#pragma unroll
        for (int ll = 0; ll < 2; ll++) {
            int f  = tid + ll * 256;
            int t  = f >> 4;              // 0..31
            int d4 = (f & 15) * 4;
            *(float4*)&Vs[t][d4] = *(const float4*)&qkv[(size_t)(kt * KT + t) * QKV_N
                                                        + (NH + KVH) * HD + kvh * HD + d4];
        }
        __syncthreads();

        // ---- S-GEMM: sc[4q][2k] = Q[4q][:] . K[:][2k] ----
        float sc[4][2];
#pragma unroll
        for (int i = 0; i < 4; i++) { sc[i][0] = 0.f; sc[i][1] = 0.f; }

#pragma unroll 8
        for (int d = 0; d < HD; d++) {
            float4 qv = *(const float4*)&Qs[d][ty * 4];
            float2 kv = *(const float2*)&Ks[d][tx * 2];
            sc[0][0] = fmaf(qv.x, kv.x, sc[0][0]);
            sc[0][1] = fmaf(qv.x, kv.y, sc[0][1]);
            sc[1][0] = fmaf(qv.y, kv.x, sc[1][0]);
            sc[1][1] = fmaf(qv.y, kv.y, sc[1][1]);
            sc[2][0] = fmaf(qv.z, kv.x, sc[2][0]);
            sc[2][1] = fmaf(qv.z, kv.y, sc[2][1]);
            sc[3][0] = fmaf(qv.w, kv.x, sc[3][0]);
            sc[3][1] = fmaf(qv.w, kv.y, sc[3][1]);
        }

        // ---- Causal mask (only near-diagonal tiles) ----
        if (kt * KT + KT - 1 > qt * QT) {
#pragma unroll
            for (int i = 0; i < 4; i++) {
                int gq = qt * QT + ty * 4 + i;
#pragma unroll
                for (int j = 0; j < 2; j++) {
                    int gk = kt * KT + tx * 2 + j;
                    if (gk > gq) sc[i][j] = -1e30f;
                }
            }
        }

        // ---- Online softmax per row (reduce across 16 tx lanes) ----
#pragma unroll
        for (int i = 0; i < 4; i++) {
            float rm = fmaxf(sc[i][0], sc[i][1]);
#pragma unroll
            for (int s = 1; s < 16; s <<= 1)
                rm = fmaxf(rm, __shfl_xor_sync(0xffffffffu, rm, s));
            float mnew = fmaxf(m[i], rm);
            float alpha = __expf(m[i] - mnew);
            float p0 = __expf(sc[i][0] - mnew);
            float p1 = __expf(sc[i][1] - mnew);
            sc[i][0] = p0; sc[i][1] = p1;
            float rs = p0 + p1;
#pragma unroll
            for (int s = 1; s < 16; s <<= 1)
                rs += __shfl_xor_sync(0xffffffffu, rs, s);
            l[i] = l[i] * alpha + rs;
            m[i] = mnew;
            o4[i].x *= alpha; o4[i].y *= alpha;
            o4[i].z *= alpha; o4[i].w *= alpha;
        }

        // ---- Write P to smem: Ps[k][q] ----
#pragma unroll
        for (int j = 0; j < 2; j++) {
            float4 pv = make_float4(sc[0][j], sc[1][j], sc[2][j], sc[3][j]);
            *(float4*)&Ps[tx * 2 + j][ty * 4] = pv;
        }
        __syncthreads();

        // ---- PV-GEMM: O[4q][4d] += P[4q][k] * V[k][4d] ----
#pragma unroll 4
        for (int k = 0; k < KT; k++) {
            float4 pv = *(const float4*)&Ps[k][ty * 4];
            float4 vv = *(const float4*)&Vs[k][tx * 4];
            o4[0].x = fmaf(pv.x, vv.x, o4[0].x);
            o4[0].y = fmaf(pv.x, vv.y, o4[0].y);
            o4[0].z = fmaf(pv.x, vv.z, o4[0].z);
            o4[0].w = fmaf(pv.x, vv.w, o4[0].w);
            o4[1].x = fmaf(pv.y, vv.x, o4[1].x);
            o4[1].y = fmaf(pv.y, vv.y, o4[1].y);
            o4[1].z = fmaf(pv.y, vv.z, o4[1].z);
            o4[1].w = fmaf(pv.y, vv.w, o4[1].w);
            o4[2].x = fmaf(pv.z, vv.x, o4[2].x);
            o4[2].y = fmaf(pv.z, vv.y, o4[2].y);
            o4[2].z = fmaf(pv.z, vv.z, o4[2].z);
            o4[2].w = fmaf(pv.z, vv.w, o4[2].w);
            o4[3].x = fmaf(pv.w, vv.x, o4[3].x);
            o4[3].y = fmaf(pv.w, vv.y, o4[3].y);
            o4[3].z = fmaf(pv.w, vv.z, o4[3].z);
            o4[3].w = fmaf(pv.w, vv.w, o4[3].w);
        }
    }

    // ---- Output: rows qt*64+ty*4+i, cols h*64 + tx*4 ----
#pragma unroll
    for (int i = 0; i < 4; i++) {
        float inv = 1.f / l[i];
        float4 v = o4[i];
        v.x *= inv; v.y *= inv; v.z *= inv; v.w *= inv;
        *(float4*)&attn_out[(size_t)(qt * QT + ty * 4 + i) * HID + h * HD + tx * 4] = v;
    }
}

// ---------------------------------------------------------------------------
// Launch
// ---------------------------------------------------------------------------
extern "C" void kernel_launch(void* const* d_in, const int* in_sizes, int n_in,
                              void* d_out, int out_size)
{
    const float* x     = (const float*)d_in[0];   // [1,2048,2048]
    const float* w_qkv = (const float*)d_in[1];   // [3072,2048]
    const float* w_o   = (const float*)d_in[2];   // [2048,2048]
    float* out = (float*)d_out;                   // [1,2048,2048]

    float* qkv_buf = nullptr;
    float* attn_buf = nullptr;
    cudaGetSymbolAddress((void**)&qkv_buf, g_qkv);
    cudaGetSymbolAddress((void**)&attn_buf, g_attn);

    // 1) QKV projection
    {
        dim3 grid(QKV_N / BN, S_LEN / BM);
        sgemm_nt<<<grid, 256>>>(x, w_qkv, qkv_buf, S_LEN, QKV_N, HID);
    }

    // 2) RoPE in place
    {
        int total = S_LEN * (NH + KVH) * (HD / 2);
        rope_kernel<<<(total + 255) / 256, 256>>>(qkv_buf);
    }

    // 3) Causal GQA attention
    {
        dim3 grid(S_LEN / QT, NH);
        attn_kernel<<<grid, 256>>>(qkv_buf, attn_buf);
    }

    // 4) Output projection
    {
        dim3 grid(HID / BN, S_LEN / BM);
        sgemm_nt<<<grid, 256>>>(attn_buf, w_o, out, S_LEN, HID, HID);
    }
}